// round 1
// baseline (speedup 1.0000x reference)
#include <cuda_runtime.h>

// Scratch accumulators: [0]=sum|r-t|, [1]=sum g, [2]=sum|g-mu|
__device__ double g_acc[3];

static __device__ __forceinline__ float warp_reduce(float v) {
    #pragma unroll
    for (int o = 16; o > 0; o >>= 1) v += __shfl_down_sync(0xFFFFFFFFu, v, o);
    return v;
}

static __device__ __forceinline__ void block_reduce_atomic(float v, int slot) {
    __shared__ float sh[32];
    int lane = threadIdx.x & 31;
    int wid  = threadIdx.x >> 5;
    v = warp_reduce(v);
    if (lane == 0) sh[wid] = v;
    __syncthreads();
    int nw = blockDim.x >> 5;
    if (wid == 0) {
        float x = (lane < nw) ? sh[lane] : 0.0f;
        x = warp_reduce(x);
        if (lane == 0) atomicAdd(&g_acc[slot], (double)x);
    }
}

__global__ void k_init() {
    g_acc[0] = 0.0; g_acc[1] = 0.0; g_acc[2] = 0.0;
}

// sum |r - t|  (reads 128 MB)
__global__ void k_rt(const float4* __restrict__ r, const float4* __restrict__ t, int n4) {
    float s = 0.0f;
    int stride = gridDim.x * blockDim.x;
    for (int i = blockIdx.x * blockDim.x + threadIdx.x; i < n4; i += stride) {
        float4 a = r[i];
        float4 b = t[i];
        s += fabsf(a.x - b.x) + fabsf(a.y - b.y) + fabsf(a.z - b.z) + fabsf(a.w - b.w);
    }
    block_reduce_atomic(s, 0);
}

// sum g  (reads 64 MB; leaves g resident in L2 for k_dev)
__global__ void k_g(const float4* __restrict__ g, int n4) {
    float s = 0.0f;
    int stride = gridDim.x * blockDim.x;
    for (int i = blockIdx.x * blockDim.x + threadIdx.x; i < n4; i += stride) {
        float4 a = g[i];
        s += a.x + a.y + a.z + a.w;
    }
    block_reduce_atomic(s, 1);
}

// sum |g - mu|  (should hit mostly in L2)
__global__ void k_dev(const float4* __restrict__ g, int n4, float inv_n) {
    float mu = (float)(g_acc[1] * (double)inv_n);
    float s = 0.0f;
    int stride = gridDim.x * blockDim.x;
    for (int i = blockIdx.x * blockDim.x + threadIdx.x; i < n4; i += stride) {
        float4 a = g[i];
        s += fabsf(a.x - mu) + fabsf(a.y - mu) + fabsf(a.z - mu) + fabsf(a.w - mu);
    }
    block_reduce_atomic(s, 2);
}

__global__ void k_fin(float* __restrict__ out, float inv_n) {
    double n_inv = (double)inv_n;
    out[0] = (float)(g_acc[0] * n_inv + 100.0 * (g_acc[2] * n_inv));
}

extern "C" void kernel_launch(void* const* d_in, const int* in_sizes, int n_in,
                              void* d_out, int out_size) {
    const float* resnet = (const float*)d_in[0];
    const float* gru    = (const float*)d_in[1];
    const float* target = (const float*)d_in[2];
    float* out = (float*)d_out;

    const int n  = in_sizes[0];          // 16777216
    const int n4 = n >> 2;               // float4 count
    const float inv_n = 1.0f / (float)n;

    const int block = 256;
    const int grid  = 148 * 8;           // 1184 CTAs, full-chip streaming

    k_init<<<1, 1>>>();
    k_rt <<<grid, block>>>((const float4*)resnet, (const float4*)target, n4);
    k_g  <<<grid, block>>>((const float4*)gru, n4);
    k_dev<<<grid, block>>>((const float4*)gru, n4, inv_n);
    k_fin<<<1, 1>>>(out, inv_n);
}

// round 2
// speedup vs baseline: 1.0149x; 1.0149x over previous
#include <cuda_runtime.h>

// Scratch: [0]=sum|r-t|, [1]=sum g, [2]=sum|g-mu|
__device__ double g_acc[3];
__device__ unsigned int g_bar[2];

static __device__ __forceinline__ float warp_reduce(float v) {
    #pragma unroll
    for (int o = 16; o > 0; o >>= 1) v += __shfl_down_sync(0xFFFFFFFFu, v, o);
    return v;
}

// block reduce -> one double atomicAdd into g_acc[slot]
static __device__ __forceinline__ void block_reduce_atomic(float v, int slot) {
    __shared__ float sh[16];
    int lane = threadIdx.x & 31;
    int wid  = threadIdx.x >> 5;
    v = warp_reduce(v);
    if (lane == 0) sh[wid] = v;
    __syncthreads();
    if (wid == 0) {
        float x = (lane < (blockDim.x >> 5)) ? sh[lane] : 0.0f;
        x = warp_reduce(x);
        if (lane == 0) atomicAdd(&g_acc[slot], (double)x);
    }
    __syncthreads();   // sh reused across phases
}

__global__ void k_init() {
    g_acc[0] = 0.0; g_acc[1] = 0.0; g_acc[2] = 0.0;
    g_bar[0] = 0u;  g_bar[1] = 0u;
}

__global__ void __launch_bounds__(512, 2)
k_fused(const float4* __restrict__ r, const float4* __restrict__ t,
        const float4* __restrict__ g, float* __restrict__ out,
        int n4, unsigned int nCTA) {
    const int tid    = blockIdx.x * blockDim.x + threadIdx.x;
    const int stride = gridDim.x * blockDim.x;

    // ---- Phase 0: sum |r - t|  (128 MB DRAM stream) ----
    float s0 = 0.0f;
    #pragma unroll 4
    for (int i = tid; i < n4; i += stride) {
        float4 a = r[i];
        float4 b = t[i];
        s0 += fabsf(a.x - b.x) + fabsf(a.y - b.y) + fabsf(a.z - b.z) + fabsf(a.w - b.w);
    }
    block_reduce_atomic(s0, 0);

    // ---- Phase 1: sum g  (64 MB DRAM stream; leaves g hot in L2) ----
    float s1 = 0.0f;
    #pragma unroll 4
    for (int i = tid; i < n4; i += stride) {
        float4 a = g[i];
        s1 += (a.x + a.y) + (a.z + a.w);
    }
    block_reduce_atomic(s1, 1);

    // ---- Grid barrier 1: all partial g-sums visible ----
    if (threadIdx.x == 0) {
        __threadfence();
        atomicAdd(&g_bar[0], 1u);
        while (*(volatile unsigned int*)&g_bar[0] < nCTA) { __nanosleep(64); }
    }
    __syncthreads();

    const double n_d = (double)n4 * 4.0;
    const float mu = (float)(*(volatile double*)&g_acc[1] / n_d);

    // ---- Phase 2: sum |g - mu|  (re-read g from L2) ----
    float s2 = 0.0f;
    #pragma unroll 4
    for (int i = tid; i < n4; i += stride) {
        float4 a = g[i];
        s2 += fabsf(a.x - mu) + fabsf(a.y - mu) + fabsf(a.z - mu) + fabsf(a.w - mu);
    }
    block_reduce_atomic(s2, 2);

    // ---- Exit ticket: last CTA to arrive finalizes the scalar ----
    if (threadIdx.x == 0) {
        __threadfence();
        unsigned int tkt = atomicAdd(&g_bar[1], 1u);
        if (tkt == nCTA - 1u) {
            double a0 = *(volatile double*)&g_acc[0];
            double a2 = *(volatile double*)&g_acc[2];
            out[0] = (float)((a0 + 100.0 * a2) / n_d);
        }
    }
}

extern "C" void kernel_launch(void* const* d_in, const int* in_sizes, int n_in,
                              void* d_out, int out_size) {
    const float* resnet = (const float*)d_in[0];
    const float* gru    = (const float*)d_in[1];
    const float* target = (const float*)d_in[2];
    float* out = (float*)d_out;

    const int n  = in_sizes[0];
    const int n4 = n >> 2;

    const int block = 512;
    const unsigned int grid = 148u * 2u;   // exactly 2 CTAs/SM, co-resident (launch_bounds enforces)

    k_init<<<1, 1>>>();
    k_fused<<<grid, block>>>((const float4*)resnet, (const float4*)target,
                             (const float4*)gru, out, n4, grid);
}

// round 3
// speedup vs baseline: 1.3668x; 1.3467x over previous
#include <cuda_runtime.h>

// Scratch: [0]=sum|r-t|, [1]=sum g, [2]=sum|g-mu|
// Zero-initialized at module load; reset by the exit-ticket CTA each run.
__device__ double g_acc[3];
// Monotone counters (never reset -> no barrier-reset deadlock across graph replays)
__device__ unsigned int g_bar[2];   // [0] mid grid barrier, [1] exit ticket

static __device__ __forceinline__ float warp_reduce(float v) {
    #pragma unroll
    for (int o = 16; o > 0; o >>= 1) v += __shfl_down_sync(0xFFFFFFFFu, v, o);
    return v;
}

__global__ void __launch_bounds__(512, 3)
k_fused(const float4* __restrict__ r, const float4* __restrict__ t,
        const float4* __restrict__ g, float* __restrict__ out,
        int n4, unsigned int nCTA) {
    const int tid    = blockIdx.x * blockDim.x + threadIdx.x;
    const int stride = gridDim.x * blockDim.x;
    const int lane   = threadIdx.x & 31;
    const int wid    = threadIdx.x >> 5;
    const int nwarp  = blockDim.x >> 5;

    __shared__ float sh0[16], sh1[16];
    __shared__ float s_mu;

    // ---- Merged stream: sum|r-t| and sum g in one 192 MB pass ----
    // r,t are evict-first (.cs) so the g stream stays resident in L2.
    float s0 = 0.0f, s1 = 0.0f;
    #pragma unroll 2
    for (int i = tid; i < n4; i += stride) {
        float4 a = __ldcs(&r[i]);
        float4 b = __ldcs(&t[i]);
        float4 c = g[i];
        s0 += fabsf(a.x - b.x) + fabsf(a.y - b.y) + fabsf(a.z - b.z) + fabsf(a.w - b.w);
        s1 += (c.x + c.y) + (c.z + c.w);
    }

    // Combined block reduce for s0, s1 (single sync)
    s0 = warp_reduce(s0);
    s1 = warp_reduce(s1);
    if (lane == 0) { sh0[wid] = s0; sh1[wid] = s1; }
    __syncthreads();
    if (wid == 0) {
        float x0 = (lane < nwarp) ? sh0[lane] : 0.0f;
        float x1 = (lane < nwarp) ? sh1[lane] : 0.0f;
        x0 = warp_reduce(x0);
        x1 = warp_reduce(x1);
        if (lane == 0) {
            atomicAdd(&g_acc[0], (double)x0);
            atomicAdd(&g_acc[1], (double)x1);
        }
    }

    // ---- Epoch grid barrier (monotone counter; replay-safe) ----
    if (threadIdx.x == 0) {
        __threadfence();
        unsigned int tkt    = atomicAdd(&g_bar[0], 1u);
        unsigned int target = (tkt / nCTA + 1u) * nCTA;
        while (*(volatile unsigned int*)&g_bar[0] < target) { __nanosleep(64); }
        double sum = *(volatile double*)&g_acc[1];
        s_mu = (float)(sum / ((double)n4 * 4.0));
    }
    __syncthreads();
    const float mu = s_mu;

    // ---- Phase 2: sum |g - mu|  (g should be L2-resident) ----
    float s2 = 0.0f;
    #pragma unroll 4
    for (int i = tid; i < n4; i += stride) {
        float4 c = g[i];
        s2 += fabsf(c.x - mu) + fabsf(c.y - mu) + fabsf(c.z - mu) + fabsf(c.w - mu);
    }
    s2 = warp_reduce(s2);
    if (lane == 0) sh0[wid] = s2;
    __syncthreads();
    if (wid == 0) {
        float x = (lane < nwarp) ? sh0[lane] : 0.0f;
        x = warp_reduce(x);
        if (lane == 0) atomicAdd(&g_acc[2], (double)x);
    }

    // ---- Exit ticket: last CTA finalizes scalar + resets accumulators ----
    if (threadIdx.x == 0) {
        __threadfence();
        unsigned int tkt = atomicAdd(&g_bar[1], 1u);
        if ((tkt + 1u) % nCTA == 0u) {
            double a0  = *(volatile double*)&g_acc[0];
            double a2  = *(volatile double*)&g_acc[2];
            double n_d = (double)n4 * 4.0;
            out[0] = (float)((a0 + 100.0 * a2) / n_d);
            g_acc[0] = 0.0; g_acc[1] = 0.0; g_acc[2] = 0.0;  // ready for next replay
            __threadfence();
        }
    }
}

extern "C" void kernel_launch(void* const* d_in, const int* in_sizes, int n_in,
                              void* d_out, int out_size) {
    const float* resnet = (const float*)d_in[0];
    const float* gru    = (const float*)d_in[1];
    const float* target = (const float*)d_in[2];
    float* out = (float*)d_out;

    const int n  = in_sizes[0];
    const int n4 = n >> 2;

    const int block = 512;
    const unsigned int grid = 148u * 3u;   // 48 warps/SM via launch_bounds(512,3)

    k_fused<<<grid, block>>>((const float4*)resnet, (const float4*)target,
                             (const float4*)gru, out, n4, grid);
}